// round 4
// baseline (speedup 1.0000x reference)
#include <cuda_runtime.h>
#include <math.h>

#define TT 2048
#define NCTA 128

__device__ float g_MT[256 * 1024];                    // folded init matrix, [d][j]
__device__ float g_abias[1024];                       // folded layer0 bias
__device__ float g_A0[(size_t)TT * 32 * 1024];        // layer0 input gates [t][b][j]
__device__ float g_h0buf[3][32 * 256];
__device__ float g_h1buf[3][32 * 256];
__device__ unsigned g_bar_count = 0;
__device__ unsigned g_bar_gen = 0;

__device__ __forceinline__ float sigf(float x) {
    return __fdividef(1.f, 1.f + __expf(-x));
}

// ---- K1a: MT[d][j] = sum_h Wih0[j,h] * Winit[h,d] --------------------------
__global__ void k1_mt(const float* __restrict__ Wih, const float* __restrict__ Winit) {
    int d = (blockIdx.x & 7) * 32 + (threadIdx.x & 31);
    int j = (blockIdx.x >> 3) * 8 + (threadIdx.x >> 5);
    const float* wr = Wih + (size_t)j * 256;
    float s = 0.f;
#pragma unroll 4
    for (int h = 0; h < 256; ++h)
        s = fmaf(wr[h], Winit[(size_t)h * 256 + d], s);
    g_MT[(size_t)d * 1024 + j] = s;
}

// ---- K1b: abias[j] = Wih0[j,:]·b_init + bih0[j] + bhh0[j] ------------------
__global__ void k1_bias(const float* __restrict__ Wih, const float* __restrict__ binit,
                        const float* __restrict__ bih, const float* __restrict__ bhh) {
    int j = blockIdx.x * 256 + threadIdx.x;
    const float* wr = Wih + (size_t)j * 256;
    float s = bih[j] + bhh[j];
#pragma unroll 4
    for (int h = 0; h < 256; ++h) s = fmaf(wr[h], binit[h], s);
    g_abias[j] = s;
}

// ---- K2: A0 = input @ MT + abias  (65536 x 1024 x 256 SGEMM) ---------------
__global__ __launch_bounds__(256) void k2_gemm(const float* __restrict__ A) {
    __shared__ float As[16][132];
    __shared__ float Bs[16][64];
    const int tid = threadIdx.x;
    const int rowBase = blockIdx.y * 128;
    const int colBase = blockIdx.x * 64;
    const int ty = tid >> 4, tx = tid & 15;

    float acc[8][4];
#pragma unroll
    for (int i = 0; i < 8; ++i)
#pragma unroll
        for (int c = 0; c < 4; ++c) acc[i][c] = 0.f;

    for (int kt = 0; kt < 256; kt += 16) {
#pragma unroll
        for (int rep = 0; rep < 2; ++rep) {
            int e = tid + rep * 256;
            int m = e >> 2, q = e & 3;
            float4 v = *(const float4*)(A + (size_t)(rowBase + m) * 256 + kt + q * 4);
            As[q * 4 + 0][m] = v.x; As[q * 4 + 1][m] = v.y;
            As[q * 4 + 2][m] = v.z; As[q * 4 + 3][m] = v.w;
        }
        {
            int kr = tid >> 4, q = tid & 15;
            *(float4*)&Bs[kr][q * 4] =
                *(const float4*)(g_MT + (size_t)(kt + kr) * 1024 + colBase + q * 4);
        }
        __syncthreads();
#pragma unroll
        for (int k = 0; k < 16; ++k) {
            float4 bv = *(float4*)&Bs[k][tx * 4];
            float4 a0 = *(float4*)&As[k][ty * 8];
            float4 a1 = *(float4*)&As[k][ty * 8 + 4];
#define FM(i, av) acc[i][0]=fmaf(av,bv.x,acc[i][0]); acc[i][1]=fmaf(av,bv.y,acc[i][1]); \
                  acc[i][2]=fmaf(av,bv.z,acc[i][2]); acc[i][3]=fmaf(av,bv.w,acc[i][3]);
            FM(0, a0.x) FM(1, a0.y) FM(2, a0.z) FM(3, a0.w)
            FM(4, a1.x) FM(5, a1.y) FM(6, a1.z) FM(7, a1.w)
#undef FM
        }
        __syncthreads();
    }
    float4 bias = *(const float4*)(g_abias + colBase + tx * 4);
#pragma unroll
    for (int i = 0; i < 8; ++i) {
        float4 r;
        r.x = acc[i][0] + bias.x; r.y = acc[i][1] + bias.y;
        r.z = acc[i][2] + bias.z; r.w = acc[i][3] + bias.w;
        *(float4*)(g_A0 + (size_t)(rowBase + ty * 8 + i) * 1024 + colBase + tx * 4) = r;
    }
}

// ---- K3: persistent recurrent kernel (one grid barrier per step) -----------
// 128 CTAs x 256 thr, 1 CTA/SM. CTA owns hidden cols {2bx, 2bx+1} of BOTH
// layers. Phase p computes h1[p-1] and h0[p] (both need only h0[p-1], h1[p-2]).
// SMEM floats: sw 0..6240 (3 mats x 8 rows x 260), sh0 6240, sh1 14560,
// sb1 22880, sc0 22888, sc1 22952, total 23016 floats = 92064 B.
__global__ __launch_bounds__(256, 1) void k3_rec(
    const float* __restrict__ Wih, const float* __restrict__ Whh,
    const float* __restrict__ bih, const float* __restrict__ bhh,
    const float* __restrict__ h0in, const float* __restrict__ c0in,
    float* __restrict__ out)
{
    extern __shared__ float sm[];
    float* sw  = sm;
    float* sh0 = sm + 6240;
    float* sh1 = sm + 14560;
    float* sb1 = sm + 22880;
    float* sc0 = sm + 22888;
    float* sc1 = sm + 22952;

    const int tid = threadIdx.x;
    const int hc0 = blockIdx.x * 2;
    const int lane = tid & 31, wp = tid >> 5;
    const int r = lane & 7;                 // gate row: g = r>>1, u = r&1
    const int bg = wp * 4 + (lane >> 3);    // batch 0..31

    // persistent weights: m0=Whh0, m1=Wih1, m2=Whh1 (layer stride 262144)
    for (int e = tid; e < 1536; e += 256) {
        int m = e >> 9, rr = (e >> 6) & 7, q = e & 63;
        int j = (rr >> 1) * 256 + hc0 + (rr & 1);
        const float* base = (m == 0) ? (Whh + (size_t)j * 256)
                          : (m == 1) ? (Wih + 262144 + (size_t)j * 256)
                                     : (Whh + 262144 + (size_t)j * 256);
        *(float4*)&sw[(m * 8 + rr) * 260 + q * 4] = *(const float4*)(base + q * 4);
    }
    if (tid < 8) {
        int j = (tid >> 1) * 256 + hc0 + (tid & 1);
        sb1[tid] = bih[1024 + j] + bhh[1024 + j];
    }
    if (tid < 64) {
        int b = tid >> 1, u = tid & 1;
        sc0[tid] = c0in[b * 256 + hc0 + u];
        sc1[tid] = c0in[8192 + b * 256 + hc0 + u];
    }
    __syncthreads();

    const float b1 = sb1[r];
    const float* wr0 = sw + r * 260;
    const float* wr1 = sw + (8 + r) * 260;
    const float* wr2 = sw + (16 + r) * 260;
    const float* hb0 = sh0 + bg * 260;
    const float* hb1 = sh1 + bg * 260;
    const size_t a0idx = (size_t)bg * 1024 + (r >> 1) * 256 + hc0 + (r & 1);

    for (int p = 0; p <= TT; ++p) {
        float a0v = 0.f;
        if (p < TT) a0v = __ldcs(g_A0 + (size_t)p * 32768 + a0idx);

        const float* s0 = (p == 0) ? h0in : g_h0buf[(p - 1) % 3];
        const float* s1 = (p <= 1) ? (h0in + 8192) : g_h1buf[(p - 1) % 3];
#pragma unroll
        for (int i = 0; i < 8; ++i) {
            int f4 = tid + i * 256;
            int b = f4 >> 6, k4 = f4 & 63;
            float4 v0 = __ldcg((const float4*)(s0 + b * 256 + k4 * 4));
            float4 v1 = __ldcg((const float4*)(s1 + b * 256 + k4 * 4));
            *(float4*)&sh0[b * 260 + k4 * 4] = v0;
            *(float4*)&sh1[b * 260 + k4 * 4] = v1;
        }
        __syncthreads();

        float acc0 = 0.f, acc1 = 0.f, acc2 = 0.f;
#pragma unroll 8
        for (int k = 0; k < 64; ++k) {
            float4 h0v = *(const float4*)(hb0 + k * 4);
            float4 h1v = *(const float4*)(hb1 + k * 4);
            float4 w0 = *(const float4*)(wr0 + k * 4);
            float4 w1 = *(const float4*)(wr1 + k * 4);
            float4 w2 = *(const float4*)(wr2 + k * 4);
            acc0 = fmaf(h0v.x, w0.x, acc0); acc0 = fmaf(h0v.y, w0.y, acc0);
            acc0 = fmaf(h0v.z, w0.z, acc0); acc0 = fmaf(h0v.w, w0.w, acc0);
            acc1 = fmaf(h0v.x, w1.x, acc1); acc1 = fmaf(h0v.y, w1.y, acc1);
            acc1 = fmaf(h0v.z, w1.z, acc1); acc1 = fmaf(h0v.w, w1.w, acc1);
            acc2 = fmaf(h1v.x, w2.x, acc2); acc2 = fmaf(h1v.y, w2.y, acc2);
            acc2 = fmaf(h1v.z, w2.z, acc2); acc2 = fmaf(h1v.w, w2.w, acc2);
        }
        float gv0 = a0v + acc0;            // layer0 gate (bias folded into A0)
        float gv1 = acc1 + acc2 + b1;      // layer1 gate
        float f0  = __shfl_down_sync(0xffffffffu, gv0, 2);
        float gg0 = __shfl_down_sync(0xffffffffu, gv0, 4);
        float o0  = __shfl_down_sync(0xffffffffu, gv0, 6);
        float f1  = __shfl_down_sync(0xffffffffu, gv1, 2);
        float gg1 = __shfl_down_sync(0xffffffffu, gv1, 4);
        float o1  = __shfl_down_sync(0xffffffffu, gv1, 6);
        if (r < 2) {
            int ci = bg * 2 + r, col = hc0 + r;
            if (p < TT) {
                float c = sc0[ci];
                float cn = fmaf(sigf(f0), c, sigf(gv0) * tanhf(gg0));
                float hn = sigf(o0) * tanhf(cn);
                sc0[ci] = cn;
                __stcg(g_h0buf[p % 3] + bg * 256 + col, hn);
            }
            if (p >= 1) {
                float c = sc1[ci];
                float cn = fmaf(sigf(f1), c, sigf(gv1) * tanhf(gg1));
                float hn = sigf(o1) * tanhf(cn);
                sc1[ci] = cn;
                __stcg(g_h1buf[p % 3] + bg * 256 + col, hn);
                out[(size_t)(p - 1) * 16384 + bg * 512 + col] = hn;
            }
        }
        // ---- grid barrier (sense-reversing; all 128 CTAs co-resident) ----
        __syncthreads();
        if (tid == 0) {
            __threadfence();
            unsigned gen = *(volatile unsigned*)&g_bar_gen;
            unsigned a = atomicAdd(&g_bar_count, 1u);
            if (a == NCTA - 1) {
                *(volatile unsigned*)&g_bar_count = 0;
                __threadfence();
                atomicAdd(&g_bar_gen, 1u);
            } else {
                while (*(volatile unsigned*)&g_bar_gen == gen) { }
            }
        }
        __syncthreads();
    }
}

// ---- K4: backward half = h1[T-1] broadcast over t --------------------------
__global__ void k4_fill(float* __restrict__ out) {
    size_t i = (size_t)blockIdx.x * 256 + threadIdx.x;   // over 2048*32*64 f4
    int u4 = (int)(i & 63);
    size_t tb = i >> 6;
    int b = (int)(tb & 31);
    float4 v = *(const float4*)(out + (size_t)2047 * 16384 + b * 512 + u4 * 4);
    *(float4*)(out + tb * 512 + 256 + u4 * 4) = v;
}

extern "C" void kernel_launch(void* const* d_in, const int* in_sizes, int n_in,
                              void* d_out, int out_size) {
    const float* input = (const float*)d_in[0];
    const float* Winit = (const float*)d_in[1];
    const float* binit = (const float*)d_in[2];
    const float* Wih   = (const float*)d_in[3];
    const float* Whh   = (const float*)d_in[4];
    const float* bih   = (const float*)d_in[5];
    const float* bhh   = (const float*)d_in[6];
    const float* h0in  = (const float*)d_in[7];
    const float* c0in  = (const float*)d_in[8];
    float* out = (float*)d_out;

    cudaFuncSetAttribute(k3_rec, cudaFuncAttributeMaxDynamicSharedMemorySize, 92064);

    k1_mt<<<1024, 256>>>(Wih, Winit);
    k1_bias<<<4, 256>>>(Wih, binit, bih, bhh);
    k2_gemm<<<dim3(16, 512), 256>>>(input);
    k3_rec<<<NCTA, 256, 92064>>>(Wih, Whh, bih, bhh, h0in, c0in, out);
    k4_fill<<<16384, 256>>>(out);
}